// round 1
// baseline (speedup 1.0000x reference)
#include <cuda_runtime.h>
#include <math.h>

#define BB 4
#define LL 2048
#define DD 1024
#define HH 16
#define DHH 64
#define NTOK (BB*LL)   // 8192 rows

// ---------------- scratch (device globals; no allocation allowed) ----------------
__device__ float g_h  [NTOK*DD];   // LN1 output
__device__ float g_q  [NTOK*DD];
__device__ float g_k  [NTOK*DD];
__device__ float g_v  [NTOK*DD];
__device__ float g_res[NTOK*DD];   // x + attn
__device__ float g_ln2[NTOK*DD];   // LN2 output
__device__ float g_mlp[NTOK*DD];   // GELU(ln2 @ Wo1 + bo1)

// ---------------- LayerNorm: one block per row of 1024 ----------------
__global__ void __launch_bounds__(256)
ln_kernel(const float* __restrict__ in, const float* __restrict__ gam,
          const float* __restrict__ bet, float* __restrict__ out)
{
    size_t base = (size_t)blockIdx.x * DD;
    int t4 = threadIdx.x * 4;
    float4 v = *(const float4*)&in[base + t4];
    float s  = v.x + v.y + v.z + v.w;
    float s2 = v.x*v.x + v.y*v.y + v.z*v.z + v.w*v.w;
    #pragma unroll
    for (int o = 16; o; o >>= 1) {
        s  += __shfl_xor_sync(0xffffffffu, s,  o);
        s2 += __shfl_xor_sync(0xffffffffu, s2, o);
    }
    __shared__ float rs[8], rs2[8];
    __shared__ float smu, srstd;
    int w = threadIdx.x >> 5, lane = threadIdx.x & 31;
    if (lane == 0) { rs[w] = s; rs2[w] = s2; }
    __syncthreads();
    if (threadIdx.x == 0) {
        float S = 0.f, S2 = 0.f;
        #pragma unroll
        for (int i = 0; i < 8; i++) { S += rs[i]; S2 += rs2[i]; }
        float mu  = S * (1.0f / DD);
        float var = S2 * (1.0f / DD) - mu * mu;
        smu = mu;
        srstd = rsqrtf(var + 1e-6f);
    }
    __syncthreads();
    float mu = smu, rstd = srstd;
    float4 g4 = *(const float4*)&gam[t4];
    float4 b4 = *(const float4*)&bet[t4];
    float4 o;
    o.x = (v.x - mu) * rstd * g4.x + b4.x;
    o.y = (v.y - mu) * rstd * g4.y + b4.y;
    o.z = (v.z - mu) * rstd * g4.z + b4.z;
    o.w = (v.w - mu) * rstd * g4.w + b4.w;
    *(float4*)&out[base + t4] = o;
}

// ---------------- SGEMM: C = A[M,K] @ W[K,N] + bias (+gelu) (+res) ----------------
// 128x128 tile, BK=16, 256 threads, 8x8 microtile per thread.
template<int ACT, bool RES>
__global__ void __launch_bounds__(256, 2)
sgemm_kernel(const float* __restrict__ A, const float* __restrict__ W,
             const float* __restrict__ bias, const float* __restrict__ res,
             float* __restrict__ C, int M, int N, int K)
{
    __shared__ float As[16][128];
    __shared__ float Bs[16][128];
    const int tid = threadIdx.x;
    const int tr = tid >> 4;        // 0..15
    const int tc = tid & 15;        // 0..15
    const int row0 = blockIdx.y * 128;
    const int col0 = blockIdx.x * 128;

    float acc[8][8];
    #pragma unroll
    for (int i = 0; i < 8; i++)
        #pragma unroll
        for (int j = 0; j < 8; j++) acc[i][j] = 0.f;

    for (int kt = 0; kt < K; kt += 16) {
        #pragma unroll
        for (int s = 0; s < 2; s++) {
            int idx = tid + s * 256;
            // A tile 128 rows x 16 cols, float4 along K, stored transposed
            int r  = idx >> 2;
            int c4 = (idx & 3) << 2;
            float4 av = *(const float4*)&A[(size_t)(row0 + r) * K + kt + c4];
            As[c4 + 0][r] = av.x;
            As[c4 + 1][r] = av.y;
            As[c4 + 2][r] = av.z;
            As[c4 + 3][r] = av.w;
            // B tile 16 rows x 128 cols, float4 along N
            int rb = idx >> 5;
            int cb = (idx & 31) << 2;
            *(float4*)&Bs[rb][cb] = *(const float4*)&W[(size_t)(kt + rb) * N + col0 + cb];
        }
        __syncthreads();
        #pragma unroll
        for (int kk = 0; kk < 16; kk++) {
            float ar[8], br[8];
            *(float4*)&ar[0] = *(float4*)&As[kk][tr * 8];
            *(float4*)&ar[4] = *(float4*)&As[kk][tr * 8 + 4];
            *(float4*)&br[0] = *(float4*)&Bs[kk][tc * 8];
            *(float4*)&br[4] = *(float4*)&Bs[kk][tc * 8 + 4];
            #pragma unroll
            for (int i = 0; i < 8; i++)
                #pragma unroll
                for (int j = 0; j < 8; j++)
                    acc[i][j] += ar[i] * br[j];
        }
        __syncthreads();
    }

    float bi[8];
    *(float4*)&bi[0] = *(const float4*)&bias[col0 + tc * 8];
    *(float4*)&bi[4] = *(const float4*)&bias[col0 + tc * 8 + 4];
    #pragma unroll
    for (int i = 0; i < 8; i++) {
        size_t ro = (size_t)(row0 + tr * 8 + i) * N + col0 + tc * 8;
        float o[8];
        #pragma unroll
        for (int j = 0; j < 8; j++) {
            float val = acc[i][j] + bi[j];
            if (ACT == 1)
                val = 0.5f * val * (1.0f + erff(val * 0.70710678118654752f));
            o[j] = val;
        }
        if (RES) {
            float4 r0 = *(const float4*)&res[ro];
            float4 r1 = *(const float4*)&res[ro + 4];
            o[0] += r0.x; o[1] += r0.y; o[2] += r0.z; o[3] += r0.w;
            o[4] += r1.x; o[5] += r1.y; o[6] += r1.z; o[7] += r1.w;
        }
        *(float4*)&C[ro]     = *(float4*)&o[0];
        *(float4*)&C[ro + 4] = *(float4*)&o[4];
    }
}

// ---------------- Flash attention (fp32) ----------------
// Block: 64 queries of one (b,h). 256 threads. Online softmax over K tiles of 64.
// Writes res = x + attn.
#define ATT_STRIDE 68   // 64 + 4 pad to avoid LDS bank conflicts
#define ATT_SMEM_FLOATS (4*64*ATT_STRIDE + 3*64)

__global__ void __launch_bounds__(256)
attn_kernel(const float* __restrict__ q, const float* __restrict__ k,
            const float* __restrict__ v, const int* __restrict__ mask,
            const float* __restrict__ x, float* __restrict__ res)
{
    extern __shared__ float sm[];
    float* Qs   = sm;                       // [64][68]
    float* Ks   = Qs + 64 * ATT_STRIDE;     // [64][68]
    float* Vs   = Ks + 64 * ATT_STRIDE;     // [64][68]
    float* Ss   = Vs + 64 * ATT_STRIDE;     // [64][68]
    float* mrow = Ss + 64 * ATT_STRIDE;     // [64]
    float* lrow = mrow + 64;                // [64]
    float* scl  = lrow + 64;                // [64]

    const int bh = blockIdx.y;
    const int b  = bh >> 4;
    const int h  = bh & 15;
    const int q0 = blockIdx.x * 64;

    // load Q tile
    for (int it = threadIdx.x; it < 1024; it += 256) {
        int r  = it >> 4;
        int d4 = (it & 15) << 2;
        *(float4*)&Qs[r * ATT_STRIDE + d4] =
            *(const float4*)&q[((size_t)(b * LL + q0 + r)) * DD + h * DHH + d4];
    }
    if (threadIdx.x < 64) { mrow[threadIdx.x] = -1e30f; lrow[threadIdx.x] = 0.f; }

    const int tr4 = (threadIdx.x >> 4) * 4;   // q rows
    const int tc4 = (threadIdx.x & 15) * 4;   // k cols / d cols
    float acc[4][4];
    #pragma unroll
    for (int i = 0; i < 4; i++)
        #pragma unroll
        for (int j = 0; j < 4; j++) acc[i][j] = 0.f;

    __syncthreads();

    for (int kt = 0; kt < LL; kt += 64) {
        // load K,V tiles
        for (int it = threadIdx.x; it < 1024; it += 256) {
            int r  = it >> 4;
            int d4 = (it & 15) << 2;
            size_t gidx = ((size_t)(b * LL + kt + r)) * DD + h * DHH + d4;
            *(float4*)&Ks[r * ATT_STRIDE + d4] = *(const float4*)&k[gidx];
            *(float4*)&Vs[r * ATT_STRIDE + d4] = *(const float4*)&v[gidx];
        }
        __syncthreads();

        // S = Q K^T for 4x4 microtile
        float s[4][4];
        #pragma unroll
        for (int i = 0; i < 4; i++)
            #pragma unroll
            for (int j = 0; j < 4; j++) s[i][j] = 0.f;
        #pragma unroll
        for (int d0 = 0; d0 < 64; d0 += 4) {
            float4 qa[4], kb[4];
            #pragma unroll
            for (int i = 0; i < 4; i++) qa[i] = *(const float4*)&Qs[(tr4 + i) * ATT_STRIDE + d0];
            #pragma unroll
            for (int j = 0; j < 4; j++) kb[j] = *(const float4*)&Ks[(tc4 + j) * ATT_STRIDE + d0];
            #pragma unroll
            for (int i = 0; i < 4; i++)
                #pragma unroll
                for (int j = 0; j < 4; j++)
                    s[i][j] += qa[i].x*kb[j].x + qa[i].y*kb[j].y + qa[i].z*kb[j].z + qa[i].w*kb[j].w;
        }
        // scale + mask, store to Ss
        #pragma unroll
        for (int j = 0; j < 4; j++) {
            float madd = mask[b * LL + kt + tc4 + j] ? 0.f : -1e30f;
            #pragma unroll
            for (int i = 0; i < 4; i++)
                Ss[(tr4 + i) * ATT_STRIDE + tc4 + j] = s[i][j] * 0.125f + madd;
        }
        __syncthreads();

        // online softmax: 4 threads per row, 16 cols each
        {
            int r   = threadIdx.x >> 2;
            int seg = threadIdx.x & 3;
            float* srow = &Ss[r * ATT_STRIDE + seg * 16];
            float mold = mrow[r];
            float mx = mold;
            #pragma unroll
            for (int c = 0; c < 16; c++) mx = fmaxf(mx, srow[c]);
            mx = fmaxf(mx, __shfl_xor_sync(0xffffffffu, mx, 1));
            mx = fmaxf(mx, __shfl_xor_sync(0xffffffffu, mx, 2));
            float ls = 0.f;
            #pragma unroll
            for (int c = 0; c < 16; c++) {
                float p = __expf(srow[c] - mx);
                srow[c] = p;
                ls += p;
            }
            ls += __shfl_xor_sync(0xffffffffu, ls, 1);
            ls += __shfl_xor_sync(0xffffffffu, ls, 2);
            if (seg == 0) {
                float corr = __expf(mold - mx);
                scl[r]  = corr;
                lrow[r] = lrow[r] * corr + ls;
                mrow[r] = mx;
            }
        }
        __syncthreads();

        // O = O*scl + P @ V
        #pragma unroll
        for (int i = 0; i < 4; i++) {
            float c0 = scl[tr4 + i];
            #pragma unroll
            for (int j = 0; j < 4; j++) acc[i][j] *= c0;
        }
        #pragma unroll 4
        for (int kk = 0; kk < 64; kk++) {
            float4 vv = *(const float4*)&Vs[kk * ATT_STRIDE + tc4];
            #pragma unroll
            for (int i = 0; i < 4; i++) {
                float p = Ss[(tr4 + i) * ATT_STRIDE + kk];
                acc[i][0] += p * vv.x;
                acc[i][1] += p * vv.y;
                acc[i][2] += p * vv.z;
                acc[i][3] += p * vv.w;
            }
        }
        __syncthreads();
    }

    // finalize: out = acc / l + x  -> res
    #pragma unroll
    for (int i = 0; i < 4; i++) {
        float inv = 1.0f / lrow[tr4 + i];
        size_t base = ((size_t)(b * LL + q0 + tr4 + i)) * DD + h * DHH + tc4;
        float4 xr = *(const float4*)&x[base];
        float4 o;
        o.x = acc[i][0] * inv + xr.x;
        o.y = acc[i][1] * inv + xr.y;
        o.z = acc[i][2] * inv + xr.z;
        o.w = acc[i][3] * inv + xr.w;
        *(float4*)&res[base] = o;
    }
}

// ---------------- launch ----------------
extern "C" void kernel_launch(void* const* d_in, const int* in_sizes, int n_in,
                              void* d_out, int out_size)
{
    const float* x    = (const float*)d_in[0];
    const int*   mask = (const int*)  d_in[1];
    const float* Wq   = (const float*)d_in[2];
    const float* bq   = (const float*)d_in[3];
    const float* Wk   = (const float*)d_in[4];
    const float* bk   = (const float*)d_in[5];
    const float* Wv   = (const float*)d_in[6];
    const float* bv   = (const float*)d_in[7];
    const float* g1   = (const float*)d_in[8];
    const float* b1   = (const float*)d_in[9];
    const float* g2   = (const float*)d_in[10];
    const float* b2   = (const float*)d_in[11];
    const float* Wo1  = (const float*)d_in[12];
    const float* bo1  = (const float*)d_in[13];
    const float* Wo2  = (const float*)d_in[14];
    const float* bo2  = (const float*)d_in[15];
    float* out = (float*)d_out;

    float *h_, *q_, *k_, *v_, *res_, *ln2_, *mlp_;
    cudaGetSymbolAddress((void**)&h_,   g_h);
    cudaGetSymbolAddress((void**)&q_,   g_q);
    cudaGetSymbolAddress((void**)&k_,   g_k);
    cudaGetSymbolAddress((void**)&v_,   g_v);
    cudaGetSymbolAddress((void**)&res_, g_res);
    cudaGetSymbolAddress((void**)&ln2_, g_ln2);
    cudaGetSymbolAddress((void**)&mlp_, g_mlp);

    // 1) LN1
    ln_kernel<<<NTOK, 256>>>(x, g1, b1, h_);

    // 2) Q/K/V projections
    dim3 ggrid(DD / 128, NTOK / 128);
    sgemm_kernel<0, false><<<ggrid, 256>>>(h_, Wq, bq, nullptr, q_, NTOK, DD, DD);
    sgemm_kernel<0, false><<<ggrid, 256>>>(h_, Wk, bk, nullptr, k_, NTOK, DD, DD);
    sgemm_kernel<0, false><<<ggrid, 256>>>(h_, Wv, bv, nullptr, v_, NTOK, DD, DD);

    // 3) attention + residual -> g_res
    size_t att_smem = ATT_SMEM_FLOATS * sizeof(float);
    cudaFuncSetAttribute(attn_kernel, cudaFuncAttributeMaxDynamicSharedMemorySize, (int)att_smem);
    attn_kernel<<<dim3(LL / 64, BB * HH), 256, att_smem>>>(q_, k_, v_, mask, x, res_);

    // 4) LN2
    ln_kernel<<<NTOK, 256>>>(res_, g2, b2, ln2_);

    // 5) MLP up + GELU
    sgemm_kernel<1, false><<<ggrid, 256>>>(ln2_, Wo1, bo1, nullptr, mlp_, NTOK, DD, DD);

    // 6) MLP down + bias + residual -> out
    sgemm_kernel<0, true><<<ggrid, 256>>>(mlp_, Wo2, bo2, res_, out, NTOK, DD, DD);
}

// round 3
// speedup vs baseline: 1.3004x; 1.3004x over previous
#include <cuda_runtime.h>
#include <cuda.h>
#include <cuda_bf16.h>
#include <math.h>
#include <stdint.h>

#define BB 4
#define LL 2048
#define DD 1024
#define HH 16
#define DHH 64
#define NTOK (BB*LL)   // 8192 rows

// ---------------- scratch (device globals; no allocation allowed) ----------------
__device__ float g_h  [NTOK*DD];
__device__ float g_q  [NTOK*DD];
__device__ float g_k  [NTOK*DD];
__device__ float g_v  [NTOK*DD];
__device__ float g_res[NTOK*DD];
__device__ float g_ln2[NTOK*DD];
__device__ float g_mlp[NTOK*DD];
__device__ float g_wt [5*DD*DD];   // transposed weights [N][K]

// ============================ helpers ============================
__device__ __forceinline__ uint32_t smem_u32(const void* p) {
    uint32_t a;
    asm("{ .reg .u64 t; cvta.to.shared.u64 t, %1; cvt.u32.u64 %0, t; }" : "=r"(a) : "l"(p));
    return a;
}
__device__ __forceinline__ void mma_bf16(float* c, const uint32_t* a, const uint32_t* b) {
    asm volatile(
        "mma.sync.aligned.m16n8k16.row.col.f32.bf16.bf16.f32 "
        "{%0,%1,%2,%3}, {%4,%5,%6,%7}, {%8,%9}, {%0,%1,%2,%3};"
        : "+f"(c[0]), "+f"(c[1]), "+f"(c[2]), "+f"(c[3])
        : "r"(a[0]), "r"(a[1]), "r"(a[2]), "r"(a[3]), "r"(b[0]), "r"(b[1]));
}
__device__ __forceinline__ void ldsm_x4(uint32_t* r, uint32_t addr) {
    asm volatile("ldmatrix.sync.aligned.m8n8.x4.shared.b16 {%0,%1,%2,%3}, [%4];"
        : "=r"(r[0]), "=r"(r[1]), "=r"(r[2]), "=r"(r[3]) : "r"(addr));
}
__device__ __forceinline__ void ldsm_x2(uint32_t* r, uint32_t addr) {
    asm volatile("ldmatrix.sync.aligned.m8n8.x2.shared.b16 {%0,%1}, [%2];"
        : "=r"(r[0]), "=r"(r[1]) : "r"(addr));
}

// ============ bf16x3-compensated tensor-core GEMM: C = A @ Bt^T + bias ============
// A [M,K] row-major fp32; Bt [N,K] row-major fp32 (pre-transposed weight).
// Block tile 128x128, BK=32, 8 warps (2x4), warp tile 64x32.
#define AS_STRIDE 40          // bf16 per smem row (80B: conflict-free ldmatrix)

template<int ACT, bool RES>
__global__ void __launch_bounds__(256, 2)
mgemm_kernel(const float* __restrict__ A, const float* __restrict__ Bt,
             const float* __restrict__ bias, const float* __restrict__ res,
             float* __restrict__ C, int M, int N, int K)
{
    __shared__ __align__(16) __nv_bfloat16 Ah[128][AS_STRIDE];
    __shared__ __align__(16) __nv_bfloat16 Al[128][AS_STRIDE];
    __shared__ __align__(16) __nv_bfloat16 Bh[128][AS_STRIDE];
    __shared__ __align__(16) __nv_bfloat16 Bl[128][AS_STRIDE];

    const int tid  = threadIdx.x;
    const int wid  = tid >> 5;
    const int lane = tid & 31;
    const int wm   = wid >> 2;        // 0..1  (64-row slab)
    const int wn   = wid & 3;         // 0..3  (32-col slab)
    const int row0 = blockIdx.y * 128;
    const int col0 = blockIdx.x * 128;

    float acc[4][4][4];
    #pragma unroll
    for (int i = 0; i < 4; i++)
        #pragma unroll
        for (int j = 0; j < 4; j++)
            #pragma unroll
            for (int q = 0; q < 4; q++) acc[i][j][q] = 0.f;

    // global load mapping: 256 threads x 4 float4 = 128 rows x 32 k
    const int gr = tid >> 1;              // 0..127
    const int gk = (tid & 1) * 16;        // 0 or 16
    const float* Ag = A  + (size_t)(row0 + gr) * K + gk;
    const float* Bg = Bt + (size_t)(col0 + gr) * K + gk;

    // ldmatrix lane address offsets (bytes)
    const uint32_t aoff = (uint32_t)(((lane & 15) * AS_STRIDE + ((lane >> 4) & 1) * 8) * 2);
    const uint32_t boff = (uint32_t)(((lane & 7)  * AS_STRIDE + ((lane >> 3) & 1) * 8) * 2);
    const uint32_t sAh = smem_u32(Ah), sAl = smem_u32(Al);
    const uint32_t sBh = smem_u32(Bh), sBl = smem_u32(Bl);

    for (int kt = 0; kt < K; kt += 32) {
        __syncthreads();
        #pragma unroll
        for (int j = 0; j < 4; j++) {
            float4 a = *(const float4*)(Ag + kt + 4 * j);
            __nv_bfloat16 hx = __float2bfloat16(a.x), hy = __float2bfloat16(a.y);
            __nv_bfloat16 hz = __float2bfloat16(a.z), hw = __float2bfloat16(a.w);
            *(__nv_bfloat162*)&Ah[gr][gk + 4*j]     = __nv_bfloat162(hx, hy);
            *(__nv_bfloat162*)&Ah[gr][gk + 4*j + 2] = __nv_bfloat162(hz, hw);
            *(__nv_bfloat162*)&Al[gr][gk + 4*j]     = __nv_bfloat162(
                __float2bfloat16(a.x - __bfloat162float(hx)),
                __float2bfloat16(a.y - __bfloat162float(hy)));
            *(__nv_bfloat162*)&Al[gr][gk + 4*j + 2] = __nv_bfloat162(
                __float2bfloat16(a.z - __bfloat162float(hz)),
                __float2bfloat16(a.w - __bfloat162float(hw)));
            float4 b = *(const float4*)(Bg + kt + 4 * j);
            hx = __float2bfloat16(b.x); hy = __float2bfloat16(b.y);
            hz = __float2bfloat16(b.z); hw = __float2bfloat16(b.w);
            *(__nv_bfloat162*)&Bh[gr][gk + 4*j]     = __nv_bfloat162(hx, hy);
            *(__nv_bfloat162*)&Bh[gr][gk + 4*j + 2] = __nv_bfloat162(hz, hw);
            *(__nv_bfloat162*)&Bl[gr][gk + 4*j]     = __nv_bfloat162(
                __float2bfloat16(b.x - __bfloat162float(hx)),
                __float2bfloat16(b.y - __bfloat162float(hy)));
            *(__nv_bfloat162*)&Bl[gr][gk + 4*j + 2] = __nv_bfloat162(
                __float2bfloat16(b.z - __bfloat162float(hz)),
                __float2bfloat16(b.w - __bfloat162float(hw)));
        }
        __syncthreads();

        #pragma unroll
        for (int ks = 0; ks < 32; ks += 16) {
            uint32_t ah[4][4], al[4][4];
            #pragma unroll
            for (int mt = 0; mt < 4; mt++) {
                uint32_t ro = (uint32_t)((wm * 64 + mt * 16) * (AS_STRIDE * 2)) + (uint32_t)(ks * 2);
                ldsm_x4(ah[mt], sAh + aoff + ro);
                ldsm_x4(al[mt], sAl + aoff + ro);
            }
            #pragma unroll
            for (int nt = 0; nt < 4; nt++) {
                uint32_t bh[2], bl[2];
                uint32_t ro = (uint32_t)((wn * 32 + nt * 8) * (AS_STRIDE * 2)) + (uint32_t)(ks * 2);
                ldsm_x2(bh, sBh + boff + ro);
                ldsm_x2(bl, sBl + boff + ro);
                #pragma unroll
                for (int mt = 0; mt < 4; mt++) {
                    mma_bf16(acc[mt][nt], ah[mt], bh);
                    mma_bf16(acc[mt][nt], ah[mt], bl);
                    mma_bf16(acc[mt][nt], al[mt], bh);
                }
            }
        }
    }

    // epilogue: c0=(r,c), c1=(r,c+1), c2=(r+8,c), c3=(r+8,c+1)
    const int er = lane >> 2;
    const int ec = (lane & 3) * 2;
    #pragma unroll
    for (int mt = 0; mt < 4; mt++) {
        #pragma unroll
        for (int half = 0; half < 2; half++) {
            int row = row0 + wm * 64 + mt * 16 + er + half * 8;
            float* cp = C + (size_t)row * N;
            const float* rp = res + (size_t)row * N;
            #pragma unroll
            for (int nt = 0; nt < 4; nt++) {
                int col = col0 + wn * 32 + nt * 8 + ec;
                float v0 = acc[mt][nt][half * 2 + 0] + bias[col];
                float v1 = acc[mt][nt][half * 2 + 1] + bias[col + 1];
                if (ACT == 1) {
                    v0 = 0.5f * v0 * (1.0f + erff(v0 * 0.70710678118654752f));
                    v1 = 0.5f * v1 * (1.0f + erff(v1 * 0.70710678118654752f));
                }
                if (RES) { v0 += rp[col]; v1 += rp[col + 1]; }
                float2 o; o.x = v0; o.y = v1;
                *(float2*)(cp + col) = o;
            }
        }
    }
}

// ---------------- weight transpose: out[n][k] = in[k][n], 1024x1024 ----------------
__global__ void __launch_bounds__(256)
transpose_kernel(const float* __restrict__ in, float* __restrict__ out)
{
    __shared__ float t[32][33];
    int bx = blockIdx.x * 32, by = blockIdx.y * 32;
    int x = bx + threadIdx.x;
    #pragma unroll
    for (int j = 0; j < 32; j += 8)
        t[threadIdx.y + j][threadIdx.x] = in[(size_t)(by + threadIdx.y + j) * DD + x];
    __syncthreads();
    int x2 = by + threadIdx.x;
    #pragma unroll
    for (int j = 0; j < 32; j += 8)
        out[(size_t)(bx + threadIdx.y + j) * DD + x2] = t[threadIdx.x][threadIdx.y + j];
}

// ---------------- LayerNorm ----------------
__global__ void __launch_bounds__(256)
ln_kernel(const float* __restrict__ in, const float* __restrict__ gam,
          const float* __restrict__ bet, float* __restrict__ out)
{
    size_t base = (size_t)blockIdx.x * DD;
    int t4 = threadIdx.x * 4;
    float4 v = *(const float4*)&in[base + t4];
    float s  = v.x + v.y + v.z + v.w;
    float s2 = v.x*v.x + v.y*v.y + v.z*v.z + v.w*v.w;
    #pragma unroll
    for (int o = 16; o; o >>= 1) {
        s  += __shfl_xor_sync(0xffffffffu, s,  o);
        s2 += __shfl_xor_sync(0xffffffffu, s2, o);
    }
    __shared__ float rs[8], rs2[8];
    __shared__ float smu, srstd;
    int w = threadIdx.x >> 5, lane = threadIdx.x & 31;
    if (lane == 0) { rs[w] = s; rs2[w] = s2; }
    __syncthreads();
    if (threadIdx.x == 0) {
        float S = 0.f, S2 = 0.f;
        #pragma unroll
        for (int i = 0; i < 8; i++) { S += rs[i]; S2 += rs2[i]; }
        float mu  = S * (1.0f / DD);
        float var = S2 * (1.0f / DD) - mu * mu;
        smu = mu;
        srstd = rsqrtf(var + 1e-6f);
    }
    __syncthreads();
    float mu = smu, rstd = srstd;
    float4 g4 = *(const float4*)&gam[t4];
    float4 b4 = *(const float4*)&bet[t4];
    float4 o;
    o.x = (v.x - mu) * rstd * g4.x + b4.x;
    o.y = (v.y - mu) * rstd * g4.y + b4.y;
    o.z = (v.z - mu) * rstd * g4.z + b4.z;
    o.w = (v.w - mu) * rstd * g4.w + b4.w;
    *(float4*)&out[base + t4] = o;
}

// ---------------- Flash attention (fp32) ----------------
#define ATT_STRIDE 68
#define ATT_SMEM_FLOATS (4*64*ATT_STRIDE + 3*64)

__global__ void __launch_bounds__(256)
attn_kernel(const float* __restrict__ q, const float* __restrict__ k,
            const float* __restrict__ v, const int* __restrict__ mask,
            const float* __restrict__ x, float* __restrict__ res)
{
    extern __shared__ float sm[];
    float* Qs   = sm;
    float* Ks   = Qs + 64 * ATT_STRIDE;
    float* Vs   = Ks + 64 * ATT_STRIDE;
    float* Ss   = Vs + 64 * ATT_STRIDE;
    float* mrow = Ss + 64 * ATT_STRIDE;
    float* lrow = mrow + 64;
    float* scl  = lrow + 64;

    const int bh = blockIdx.y;
    const int b  = bh >> 4;
    const int h  = bh & 15;
    const int q0 = blockIdx.x * 64;

    for (int it = threadIdx.x; it < 1024; it += 256) {
        int r  = it >> 4;
        int d4 = (it & 15) << 2;
        *(float4*)&Qs[r * ATT_STRIDE + d4] =
            *(const float4*)&q[((size_t)(b * LL + q0 + r)) * DD + h * DHH + d4];
    }
    if (threadIdx.x < 64) { mrow[threadIdx.x] = -1e30f; lrow[threadIdx.x] = 0.f; }

    const int tr4 = (threadIdx.x >> 4) * 4;
    const int tc4 = (threadIdx.x & 15) * 4;
    float acc[4][4];
    #pragma unroll
    for (int i = 0; i < 4; i++)
        #pragma unroll
        for (int j = 0; j < 4; j++) acc[i][j] = 0.f;

    __syncthreads();

    for (int kt = 0; kt < LL; kt += 64) {
        for (int it = threadIdx.x; it < 1024; it += 256) {
            int r  = it >> 4;
            int d4 = (it & 15) << 2;
            size_t gidx = ((size_t)(b * LL + kt + r)) * DD + h * DHH + d4;
            *(float4*)&Ks[r * ATT_STRIDE + d4] = *(const float4*)&k[gidx];
            *(float4*)&Vs[r * ATT_STRIDE + d4] = *(const float4*)&v[gidx];
        }
        __syncthreads();

        float s[4][4];
        #pragma unroll
        for (int i = 0; i < 4; i++)
            #pragma unroll
            for (int j = 0; j < 4; j++) s[i][j] = 0.f;
        #pragma unroll
        for (int d0 = 0; d0 < 64; d0 += 4) {
            float4 qa[4], kb[4];
            #pragma unroll
            for (int i = 0; i < 4; i++) qa[i] = *(const float4*)&Qs[(tr4 + i) * ATT_STRIDE + d0];
            #pragma unroll
            for (int j = 0; j < 4; j++) kb[j] = *(const float4*)&Ks[(tc4 + j) * ATT_STRIDE + d0];
            #pragma unroll
            for (int i = 0; i < 4; i++)
                #pragma unroll
                for (int j = 0; j < 4; j++)
                    s[i][j] += qa[i].x*kb[j].x + qa[i].y*kb[j].y + qa[i].z*kb[j].z + qa[i].w*kb[j].w;
        }
        #pragma unroll
        for (int j = 0; j < 4; j++) {
            float madd = mask[b * LL + kt + tc4 + j] ? 0.f : -1e30f;
            #pragma unroll
            for (int i = 0; i < 4; i++)
                Ss[(tr4 + i) * ATT_STRIDE + tc4 + j] = s[i][j] * 0.125f + madd;
        }
        __syncthreads();

        {
            int r   = threadIdx.x >> 2;
            int seg = threadIdx.x & 3;
            float* srow = &Ss[r * ATT_STRIDE + seg * 16];
            float mold = mrow[r];
            float mx = mold;
            #pragma unroll
            for (int c = 0; c < 16; c++) mx = fmaxf(mx, srow[c]);
            mx = fmaxf(mx, __shfl_xor_sync(0xffffffffu, mx, 1));
            mx = fmaxf(mx, __shfl_xor_sync(0xffffffffu, mx, 2));
            float ls = 0.f;
            #pragma unroll
            for (int c = 0; c < 16; c++) {
                float p = __expf(srow[c] - mx);
                srow[c] = p;
                ls += p;
            }
            ls += __shfl_xor_sync(0xffffffffu, ls, 1);
            ls += __shfl_xor_sync(0xffffffffu, ls, 2);
            if (seg == 0) {
                float corr = __expf(mold - mx);
                scl[r]  = corr;
                lrow[r] = lrow[r] * corr + ls;
                mrow[r] = mx;
            }
        }
        __syncthreads();

        #pragma unroll
        for (int i = 0; i < 4; i++) {
            float c0 = scl[tr4 + i];
            #pragma unroll
            for (int j = 0; j < 4; j++) acc[i][j] *= c0;
        }
        #pragma unroll 4
        for (int kk = 0; kk < 64; kk++) {
            float4 vv = *(const float4*)&Vs[kk * ATT_STRIDE + tc4];
            #pragma unroll
            for (int i = 0; i < 4; i++) {
                float p = Ss[(tr4 + i) * ATT_STRIDE + kk];
                acc[i][0] += p * vv.x;
                acc[i][1] += p * vv.y;
                acc[i][2] += p * vv.z;
                acc[i][3] += p * vv.w;
            }
        }
        __syncthreads();
    }

    #pragma unroll
    for (int i = 0; i < 4; i++) {
        float inv = 1.0f / lrow[tr4 + i];
        size_t base = ((size_t)(b * LL + q0 + tr4 + i)) * DD + h * DHH + tc4;
        float4 xr = *(const float4*)&x[base];
        float4 o;
        o.x = acc[i][0] * inv + xr.x;
        o.y = acc[i][1] * inv + xr.y;
        o.z = acc[i][2] * inv + xr.z;
        o.w = acc[i][3] * inv + xr.w;
        *(float4*)&res[base] = o;
    }
}

// ---------------- launch ----------------
extern "C" void kernel_launch(void* const* d_in, const int* in_sizes, int n_in,
                              void* d_out, int out_size)
{
    const float* x    = (const float*)d_in[0];
    const int*   mask = (const int*)  d_in[1];
    const float* Wq   = (const float*)d_in[2];
    const float* bq   = (const float*)d_in[3];
    const float* Wk   = (const float*)d_in[4];
    const float* bk   = (const float*)d_in[5];
    const float* Wv   = (const float*)d_in[6];
    const float* bv   = (const float*)d_in[7];
    const float* g1   = (const float*)d_in[8];
    const float* b1   = (const float*)d_in[9];
    const float* g2   = (const float*)d_in[10];
    const float* b2   = (const float*)d_in[11];
    const float* Wo1  = (const float*)d_in[12];
    const float* bo1  = (const float*)d_in[13];
    const float* Wo2  = (const float*)d_in[14];
    const float* bo2  = (const float*)d_in[15];
    float* out = (float*)d_out;

    float *h_, *q_, *k_, *v_, *res_, *ln2_, *mlp_, *wt_;
    cudaGetSymbolAddress((void**)&h_,   g_h);
    cudaGetSymbolAddress((void**)&q_,   g_q);
    cudaGetSymbolAddress((void**)&k_,   g_k);
    cudaGetSymbolAddress((void**)&v_,   g_v);
    cudaGetSymbolAddress((void**)&res_, g_res);
    cudaGetSymbolAddress((void**)&ln2_, g_ln2);
    cudaGetSymbolAddress((void**)&mlp_, g_mlp);
    cudaGetSymbolAddress((void**)&wt_,  g_wt);

    float* wtq  = wt_ + 0 * (size_t)DD * DD;
    float* wtk  = wt_ + 1 * (size_t)DD * DD;
    float* wtv  = wt_ + 2 * (size_t)DD * DD;
    float* wto1 = wt_ + 3 * (size_t)DD * DD;
    float* wto2 = wt_ + 4 * (size_t)DD * DD;

    // 0) transpose weights -> [N][K]
    dim3 tb(32, 8), tg(32, 32);
    transpose_kernel<<<tg, tb>>>(Wq,  wtq);
    transpose_kernel<<<tg, tb>>>(Wk,  wtk);
    transpose_kernel<<<tg, tb>>>(Wv,  wtv);
    transpose_kernel<<<tg, tb>>>(Wo1, wto1);
    transpose_kernel<<<tg, tb>>>(Wo2, wto2);

    // 1) LN1
    ln_kernel<<<NTOK, 256>>>(x, g1, b1, h_);

    // 2) Q/K/V projections (bf16x3 tensor-core mma)
    dim3 ggrid(DD / 128, NTOK / 128);
    mgemm_kernel<0, false><<<ggrid, 256>>>(h_, wtq, bq, h_, q_, NTOK, DD, DD);
    mgemm_kernel<0, false><<<ggrid, 256>>>(h_, wtk, bk, h_, k_, NTOK, DD, DD);
    mgemm_kernel<0, false><<<ggrid, 256>>>(h_, wtv, bv, h_, v_, NTOK, DD, DD);

    // 3) attention + residual -> g_res
    size_t att_smem = ATT_SMEM_FLOATS * sizeof(float);
    cudaFuncSetAttribute(attn_kernel, cudaFuncAttributeMaxDynamicSharedMemorySize, (int)att_smem);
    attn_kernel<<<dim3(LL / 64, BB * HH), 256, att_smem>>>(q_, k_, v_, mask, x, res_);

    // 4) LN2
    ln_kernel<<<NTOK, 256>>>(res_, g2, b2, ln2_);

    // 5) MLP up + GELU
    mgemm_kernel<1, false><<<ggrid, 256>>>(ln2_, wto1, bo1, ln2_, mlp_, NTOK, DD, DD);

    // 6) MLP down + bias + residual -> out
    mgemm_kernel<0, true><<<ggrid, 256>>>(mlp_, wto2, bo2, res_, out, NTOK, DD, DD);
}

// round 4
// speedup vs baseline: 2.7911x; 2.1463x over previous
#include <cuda_runtime.h>
#include <cuda.h>
#include <cuda_bf16.h>
#include <math.h>
#include <stdint.h>

#define BB 4
#define LL 2048
#define DD 1024
#define HH 16
#define DHH 64
#define NTOK (BB*LL)   // 8192 rows

// ---------------- scratch (device globals; no allocation allowed) ----------------
__device__ float g_h  [NTOK*DD];
__device__ float g_q  [NTOK*DD];
__device__ float g_k  [NTOK*DD];
__device__ float g_v  [NTOK*DD];
__device__ float g_res[NTOK*DD];
__device__ float g_ln2[NTOK*DD];
__device__ float g_mlp[NTOK*DD];
__device__ float g_wt [5*DD*DD];   // transposed weights [N][K]

// ============================ helpers ============================
__device__ __forceinline__ uint32_t smem_u32(const void* p) {
    uint32_t a;
    asm("{ .reg .u64 t; cvta.to.shared.u64 t, %1; cvt.u32.u64 %0, t; }" : "=r"(a) : "l"(p));
    return a;
}
__device__ __forceinline__ void mma_bf16(float* c, const uint32_t* a, const uint32_t* b) {
    asm volatile(
        "mma.sync.aligned.m16n8k16.row.col.f32.bf16.bf16.f32 "
        "{%0,%1,%2,%3}, {%4,%5,%6,%7}, {%8,%9}, {%0,%1,%2,%3};"
        : "+f"(c[0]), "+f"(c[1]), "+f"(c[2]), "+f"(c[3])
        : "r"(a[0]), "r"(a[1]), "r"(a[2]), "r"(a[3]), "r"(b[0]), "r"(b[1]));
}
__device__ __forceinline__ void ldsm_x4(uint32_t* r, uint32_t addr) {
    asm volatile("ldmatrix.sync.aligned.m8n8.x4.shared.b16 {%0,%1,%2,%3}, [%4];"
        : "=r"(r[0]), "=r"(r[1]), "=r"(r[2]), "=r"(r[3]) : "r"(addr));
}
__device__ __forceinline__ void ldsm_x2(uint32_t* r, uint32_t addr) {
    asm volatile("ldmatrix.sync.aligned.m8n8.x2.shared.b16 {%0,%1}, [%2];"
        : "=r"(r[0]), "=r"(r[1]) : "r"(addr));
}
__device__ __forceinline__ void ldsm_x2_t(uint32_t* r, uint32_t addr) {
    asm volatile("ldmatrix.sync.aligned.m8n8.x2.trans.shared.b16 {%0,%1}, [%2];"
        : "=r"(r[0]), "=r"(r[1]) : "r"(addr));
}
// hi/lo bf16 split of a float4, stored as 8 bytes each
__device__ __forceinline__ void cvt_store(__nv_bfloat16* hi, __nv_bfloat16* lo, float4 a) {
    __nv_bfloat162 h0 = __floats2bfloat162_rn(a.x, a.y);
    __nv_bfloat162 h1 = __floats2bfloat162_rn(a.z, a.w);
    __nv_bfloat162 l0 = __floats2bfloat162_rn(a.x - __bfloat162float(__low2bfloat16(h0)),
                                              a.y - __bfloat162float(__high2bfloat16(h0)));
    __nv_bfloat162 l1 = __floats2bfloat162_rn(a.z - __bfloat162float(__low2bfloat16(h1)),
                                              a.w - __bfloat162float(__high2bfloat16(h1)));
    *(__nv_bfloat162*)(hi)     = h0;
    *(__nv_bfloat162*)(hi + 2) = h1;
    *(__nv_bfloat162*)(lo)     = l0;
    *(__nv_bfloat162*)(lo + 2) = l1;
}
__device__ __forceinline__ void pack_hilo(uint32_t& ph, uint32_t& pl, float v0, float v1) {
    __nv_bfloat162 hh = __floats2bfloat162_rn(v0, v1);   // low=v0, high=v1
    float f0 = __bfloat162float(__low2bfloat16(hh));
    float f1 = __bfloat162float(__high2bfloat16(hh));
    __nv_bfloat162 ll = __floats2bfloat162_rn(v0 - f0, v1 - f1);
    ph = *(uint32_t*)&hh;
    pl = *(uint32_t*)&ll;
}

// ============ bf16x3-compensated tensor-core GEMM: C = A @ Bt^T + bias ============
#define AS_STRIDE 40          // bf16 per smem row (80B: conflict-free ldmatrix)

template<int ACT, bool RES>
__global__ void __launch_bounds__(256, 2)
mgemm_kernel(const float* __restrict__ A, const float* __restrict__ Bt,
             const float* __restrict__ bias, const float* __restrict__ res,
             float* __restrict__ C, int M, int N, int K)
{
    __shared__ __align__(16) __nv_bfloat16 Ah[128][AS_STRIDE];
    __shared__ __align__(16) __nv_bfloat16 Al[128][AS_STRIDE];
    __shared__ __align__(16) __nv_bfloat16 Bh[128][AS_STRIDE];
    __shared__ __align__(16) __nv_bfloat16 Bl[128][AS_STRIDE];

    const int tid  = threadIdx.x;
    const int wid  = tid >> 5;
    const int lane = tid & 31;
    const int wm   = wid >> 2;
    const int wn   = wid & 3;
    const int row0 = blockIdx.y * 128;
    const int col0 = blockIdx.x * 128;

    float acc[4][4][4];
    #pragma unroll
    for (int i = 0; i < 4; i++)
        #pragma unroll
        for (int j = 0; j < 4; j++)
            #pragma unroll
            for (int q = 0; q < 4; q++) acc[i][j][q] = 0.f;

    const int gr = tid >> 1;
    const int gk = (tid & 1) * 16;
    const float* Ag = A  + (size_t)(row0 + gr) * K + gk;
    const float* Bg = Bt + (size_t)(col0 + gr) * K + gk;

    const uint32_t aoff = (uint32_t)(((lane & 15) * AS_STRIDE + ((lane >> 4) & 1) * 8) * 2);
    const uint32_t boff = (uint32_t)(((lane & 7)  * AS_STRIDE + ((lane >> 3) & 1) * 8) * 2);
    const uint32_t sAh = smem_u32(Ah), sAl = smem_u32(Al);
    const uint32_t sBh = smem_u32(Bh), sBl = smem_u32(Bl);

    for (int kt = 0; kt < K; kt += 32) {
        __syncthreads();
        #pragma unroll
        for (int j = 0; j < 4; j++) {
            cvt_store(&Ah[gr][gk + 4*j], &Al[gr][gk + 4*j], *(const float4*)(Ag + kt + 4 * j));
            cvt_store(&Bh[gr][gk + 4*j], &Bl[gr][gk + 4*j], *(const float4*)(Bg + kt + 4 * j));
        }
        __syncthreads();

        #pragma unroll
        for (int ks = 0; ks < 32; ks += 16) {
            uint32_t ah[4][4], al[4][4];
            #pragma unroll
            for (int mt = 0; mt < 4; mt++) {
                uint32_t ro = (uint32_t)((wm * 64 + mt * 16) * (AS_STRIDE * 2)) + (uint32_t)(ks * 2);
                ldsm_x4(ah[mt], sAh + aoff + ro);
                ldsm_x4(al[mt], sAl + aoff + ro);
            }
            #pragma unroll
            for (int nt = 0; nt < 4; nt++) {
                uint32_t bh[2], bl[2];
                uint32_t ro = (uint32_t)((wn * 32 + nt * 8) * (AS_STRIDE * 2)) + (uint32_t)(ks * 2);
                ldsm_x2(bh, sBh + boff + ro);
                ldsm_x2(bl, sBl + boff + ro);
                #pragma unroll
                for (int mt = 0; mt < 4; mt++) {
                    mma_bf16(acc[mt][nt], ah[mt], bh);
                    mma_bf16(acc[mt][nt], ah[mt], bl);
                    mma_bf16(acc[mt][nt], al[mt], bh);
                }
            }
        }
    }

    const int er = lane >> 2;
    const int ec = (lane & 3) * 2;
    #pragma unroll
    for (int mt = 0; mt < 4; mt++) {
        #pragma unroll
        for (int half = 0; half < 2; half++) {
            int row = row0 + wm * 64 + mt * 16 + er + half * 8;
            float* cp = C + (size_t)row * N;
            const float* rp = res + (size_t)row * N;
            #pragma unroll
            for (int nt = 0; nt < 4; nt++) {
                int col = col0 + wn * 32 + nt * 8 + ec;
                float v0 = acc[mt][nt][half * 2 + 0] + bias[col];
                float v1 = acc[mt][nt][half * 2 + 1] + bias[col + 1];
                if (ACT == 1) {
                    v0 = 0.5f * v0 * (1.0f + erff(v0 * 0.70710678118654752f));
                    v1 = 0.5f * v1 * (1.0f + erff(v1 * 0.70710678118654752f));
                }
                if (RES) { v0 += rp[col]; v1 += rp[col + 1]; }
                float2 o; o.x = v0; o.y = v1;
                *(float2*)(cp + col) = o;
            }
        }
    }
}

// ---------------- weight transpose ----------------
__global__ void __launch_bounds__(256)
transpose_kernel(const float* __restrict__ in, float* __restrict__ out)
{
    __shared__ float t[32][33];
    int bx = blockIdx.x * 32, by = blockIdx.y * 32;
    int x = bx + threadIdx.x;
    #pragma unroll
    for (int j = 0; j < 32; j += 8)
        t[threadIdx.y + j][threadIdx.x] = in[(size_t)(by + threadIdx.y + j) * DD + x];
    __syncthreads();
    int x2 = by + threadIdx.x;
    #pragma unroll
    for (int j = 0; j < 32; j += 8)
        out[(size_t)(bx + threadIdx.y + j) * DD + x2] = t[threadIdx.x][threadIdx.y + j];
}

// ---------------- LayerNorm ----------------
__global__ void __launch_bounds__(256)
ln_kernel(const float* __restrict__ in, const float* __restrict__ gam,
          const float* __restrict__ bet, float* __restrict__ out)
{
    size_t base = (size_t)blockIdx.x * DD;
    int t4 = threadIdx.x * 4;
    float4 v = *(const float4*)&in[base + t4];
    float s  = v.x + v.y + v.z + v.w;
    float s2 = v.x*v.x + v.y*v.y + v.z*v.z + v.w*v.w;
    #pragma unroll
    for (int o = 16; o; o >>= 1) {
        s  += __shfl_xor_sync(0xffffffffu, s,  o);
        s2 += __shfl_xor_sync(0xffffffffu, s2, o);
    }
    __shared__ float rs[8], rs2[8];
    __shared__ float smu, srstd;
    int w = threadIdx.x >> 5, lane = threadIdx.x & 31;
    if (lane == 0) { rs[w] = s; rs2[w] = s2; }
    __syncthreads();
    if (threadIdx.x == 0) {
        float S = 0.f, S2 = 0.f;
        #pragma unroll
        for (int i = 0; i < 8; i++) { S += rs[i]; S2 += rs2[i]; }
        float mu  = S * (1.0f / DD);
        float var = S2 * (1.0f / DD) - mu * mu;
        smu = mu;
        srstd = rsqrtf(var + 1e-6f);
    }
    __syncthreads();
    float mu = smu, rstd = srstd;
    float4 g4 = *(const float4*)&gam[t4];
    float4 b4 = *(const float4*)&bet[t4];
    float4 o;
    o.x = (v.x - mu) * rstd * g4.x + b4.x;
    o.y = (v.y - mu) * rstd * g4.y + b4.y;
    o.z = (v.z - mu) * rstd * g4.z + b4.z;
    o.w = (v.w - mu) * rstd * g4.w + b4.w;
    *(float4*)&out[base + t4] = o;
}

// ============ tensor-core flash attention (bf16x3) ============
// Block: 64 queries of one (b,h). 4 warps x 16 rows. K tiles of 64.
#define ATSTRIDE 72     // bf16 per smem row (144B, conflict-free ldmatrix)
#define ATT2_SMEM (6*64*ATSTRIDE*2 + 256)

__global__ void __launch_bounds__(128, 3)
attn_mma_kernel(const float* __restrict__ q, const float* __restrict__ k,
                const float* __restrict__ v, const int* __restrict__ mask,
                const float* __restrict__ x, float* __restrict__ res)
{
    extern __shared__ char sm8[];
    __nv_bfloat16* Qh = (__nv_bfloat16*)sm8;
    __nv_bfloat16* Ql = Qh + 64 * ATSTRIDE;
    __nv_bfloat16* Kh = Ql + 64 * ATSTRIDE;
    __nv_bfloat16* Kl = Kh + 64 * ATSTRIDE;
    __nv_bfloat16* Vh = Kl + 64 * ATSTRIDE;
    __nv_bfloat16* Vl = Vh + 64 * ATSTRIDE;
    float* maskadd = (float*)(Vl + 64 * ATSTRIDE);

    const int tid  = threadIdx.x;
    const int wid  = tid >> 5;
    const int lane = tid & 31;
    const int b    = blockIdx.y >> 4;
    const int h    = blockIdx.y & 15;
    const int q0   = blockIdx.x * 64;
    const int er   = lane >> 2;
    const int qc   = lane & 3;

    // ---- load Q tile 64x64 -> hi/lo smem ----
    {
        int r = tid >> 1, c0 = (tid & 1) * 32;
        const float* qp = q + ((size_t)(b * LL + q0 + r)) * DD + h * DHH + c0;
        #pragma unroll
        for (int j = 0; j < 8; j++)
            cvt_store(&Qh[r * ATSTRIDE + c0 + 4*j], &Ql[r * ATSTRIDE + c0 + 4*j],
                      *(const float4*)(qp + 4 * j));
    }
    __syncthreads();

    // ---- persistent Q fragments ----
    const uint32_t sQh = smem_u32(Qh), sQl = smem_u32(Ql);
    const uint32_t sKh = smem_u32(Kh), sKl = smem_u32(Kl);
    const uint32_t sVh = smem_u32(Vh), sVl = smem_u32(Vl);
    const uint32_t aoff = (uint32_t)(((lane & 15) * ATSTRIDE + ((lane >> 4) & 1) * 8) * 2);
    const uint32_t boff = (uint32_t)(((lane & 7)  * ATSTRIDE + ((lane >> 3) & 1) * 8) * 2);
    uint32_t qh[4][4], qlo[4][4];
    #pragma unroll
    for (int s = 0; s < 4; s++) {
        uint32_t ro = (uint32_t)((wid * 16) * (ATSTRIDE * 2)) + (uint32_t)(s * 32);
        ldsm_x4(qh[s],  sQh + aoff + ro);
        ldsm_x4(qlo[s], sQl + aoff + ro);
    }

    float m0 = -1e30f, m1 = -1e30f, l0 = 0.f, l1 = 0.f;
    float o[8][4];
    #pragma unroll
    for (int j = 0; j < 8; j++)
        #pragma unroll
        for (int t = 0; t < 4; t++) o[j][t] = 0.f;

    for (int kt = 0; kt < LL; kt += 64) {
        __syncthreads();
        {
            int r = tid >> 1, c0 = (tid & 1) * 32;
            size_t gbase = ((size_t)(b * LL + kt + r)) * DD + h * DHH + c0;
            const float* kp = k + gbase;
            const float* vp = v + gbase;
            #pragma unroll
            for (int j = 0; j < 8; j++) {
                cvt_store(&Kh[r * ATSTRIDE + c0 + 4*j], &Kl[r * ATSTRIDE + c0 + 4*j],
                          *(const float4*)(kp + 4 * j));
                cvt_store(&Vh[r * ATSTRIDE + c0 + 4*j], &Vl[r * ATSTRIDE + c0 + 4*j],
                          *(const float4*)(vp + 4 * j));
            }
            if (tid < 64)
                maskadd[tid] = (1.0f - (float)mask[b * LL + kt + tid]) * (-1e30f);
        }
        __syncthreads();

        // ---- S = Q K^T (bf16x3) ----
        float s[8][4];
        #pragma unroll
        for (int j = 0; j < 8; j++)
            #pragma unroll
            for (int t = 0; t < 4; t++) s[j][t] = 0.f;
        #pragma unroll
        for (int ks = 0; ks < 4; ks++) {
            #pragma unroll
            for (int j = 0; j < 8; j++) {
                uint32_t kh2[2], kl2[2];
                uint32_t ro = (uint32_t)((8 * j) * (ATSTRIDE * 2)) + (uint32_t)(ks * 32);
                ldsm_x2(kh2, sKh + boff + ro);
                ldsm_x2(kl2, sKl + boff + ro);
                mma_bf16(s[j], qh[ks],  kh2);
                mma_bf16(s[j], qh[ks],  kl2);
                mma_bf16(s[j], qlo[ks], kh2);
            }
        }

        // ---- online softmax (rows er, er+8 of this warp) ----
        float mx0 = -1e30f, mx1 = -1e30f;
        #pragma unroll
        for (int j = 0; j < 8; j++) {
            float ma0 = maskadd[8 * j + 2 * qc];
            float ma1 = maskadd[8 * j + 2 * qc + 1];
            s[j][0] = s[j][0] * 0.125f + ma0;
            s[j][1] = s[j][1] * 0.125f + ma1;
            s[j][2] = s[j][2] * 0.125f + ma0;
            s[j][3] = s[j][3] * 0.125f + ma1;
            mx0 = fmaxf(mx0, fmaxf(s[j][0], s[j][1]));
            mx1 = fmaxf(mx1, fmaxf(s[j][2], s[j][3]));
        }
        mx0 = fmaxf(mx0, __shfl_xor_sync(0xffffffffu, mx0, 1));
        mx0 = fmaxf(mx0, __shfl_xor_sync(0xffffffffu, mx0, 2));
        mx1 = fmaxf(mx1, __shfl_xor_sync(0xffffffffu, mx1, 1));
        mx1 = fmaxf(mx1, __shfl_xor_sync(0xffffffffu, mx1, 2));
        float mn0 = fmaxf(m0, mx0), mn1 = fmaxf(m1, mx1);
        float c0 = __expf(m0 - mn0), c1 = __expf(m1 - mn1);
        m0 = mn0; m1 = mn1;
        float ls0 = 0.f, ls1 = 0.f;
        #pragma unroll
        for (int j = 0; j < 8; j++) {
            s[j][0] = __expf(s[j][0] - mn0);
            s[j][1] = __expf(s[j][1] - mn0);
            s[j][2] = __expf(s[j][2] - mn1);
            s[j][3] = __expf(s[j][3] - mn1);
            ls0 += s[j][0] + s[j][1];
            ls1 += s[j][2] + s[j][3];
        }
        l0 = l0 * c0 + ls0;
        l1 = l1 * c1 + ls1;
        #pragma unroll
        for (int j = 0; j < 8; j++) {
            o[j][0] *= c0; o[j][1] *= c0;
            o[j][2] *= c1; o[j][3] *= c1;
        }

        // ---- O += P @ V (bf16x3, P from S accumulators) ----
        #pragma unroll
        for (int ks = 0; ks < 4; ks++) {
            uint32_t ph[4], pl[4];
            pack_hilo(ph[0], pl[0], s[2*ks][0],   s[2*ks][1]);
            pack_hilo(ph[1], pl[1], s[2*ks][2],   s[2*ks][3]);
            pack_hilo(ph[2], pl[2], s[2*ks+1][0], s[2*ks+1][1]);
            pack_hilo(ph[3], pl[3], s[2*ks+1][2], s[2*ks+1][3]);
            uint32_t vrow = (uint32_t)((16 * ks + (lane & 7) + 8 * ((lane >> 3) & 1)) * (ATSTRIDE * 2));
            #pragma unroll
            for (int j = 0; j < 8; j++) {
                uint32_t vh2[2], vl2[2];
                uint32_t vro = vrow + (uint32_t)(16 * j);
                ldsm_x2_t(vh2, sVh + vro);
                ldsm_x2_t(vl2, sVl + vro);
                mma_bf16(o[j], ph, vh2);
                mma_bf16(o[j], ph, vl2);
                mma_bf16(o[j], pl, vh2);
            }
        }
    }

    // ---- finalize ----
    l0 += __shfl_xor_sync(0xffffffffu, l0, 1);
    l0 += __shfl_xor_sync(0xffffffffu, l0, 2);
    l1 += __shfl_xor_sync(0xffffffffu, l1, 1);
    l1 += __shfl_xor_sync(0xffffffffu, l1, 2);
    float i0 = 1.0f / l0, i1 = 1.0f / l1;

    const int row0 = q0 + wid * 16 + er;
    #pragma unroll
    for (int j = 0; j < 8; j++) {
        int col = h * DHH + 8 * j + 2 * qc;
        size_t base0 = (size_t)(b * LL + row0) * DD + col;
        size_t base1 = base0 + 8 * (size_t)DD;
        float2 r0, r1;
        r0.x = o[j][0] * i0 + x[base0];
        r0.y = o[j][1] * i0 + x[base0 + 1];
        r1.x = o[j][2] * i1 + x[base1];
        r1.y = o[j][3] * i1 + x[base1 + 1];
        *(float2*)&res[base0] = r0;
        *(float2*)&res[base1] = r1;
    }
}

// ---------------- launch ----------------
extern "C" void kernel_launch(void* const* d_in, const int* in_sizes, int n_in,
                              void* d_out, int out_size)
{
    const float* x    = (const float*)d_in[0];
    const int*   mask = (const int*)  d_in[1];
    const float* Wq   = (const float*)d_in[2];
    const float* bq   = (const float*)d_in[3];
    const float* Wk   = (const float*)d_in[4];
    const float* bk   = (const float*)d_in[5];
    const float* Wv   = (const float*)d_in[6];
    const float* bv   = (const float*)d_in[7];
    const float* g1   = (const float*)d_in[8];
    const float* b1   = (const float*)d_in[9];
    const float* g2   = (const float*)d_in[10];
    const float* b2   = (const float*)d_in[11];
    const float* Wo1  = (const float*)d_in[12];
    const float* bo1  = (const float*)d_in[13];
    const float* Wo2  = (const float*)d_in[14];
    const float* bo2  = (const float*)d_in[15];
    float* out = (float*)d_out;

    float *h_, *q_, *k_, *v_, *res_, *ln2_, *mlp_, *wt_;
    cudaGetSymbolAddress((void**)&h_,   g_h);
    cudaGetSymbolAddress((void**)&q_,   g_q);
    cudaGetSymbolAddress((void**)&k_,   g_k);
    cudaGetSymbolAddress((void**)&v_,   g_v);
    cudaGetSymbolAddress((void**)&res_, g_res);
    cudaGetSymbolAddress((void**)&ln2_, g_ln2);
    cudaGetSymbolAddress((void**)&mlp_, g_mlp);
    cudaGetSymbolAddress((void**)&wt_,  g_wt);

    float* wtq  = wt_ + 0 * (size_t)DD * DD;
    float* wtk  = wt_ + 1 * (size_t)DD * DD;
    float* wtv  = wt_ + 2 * (size_t)DD * DD;
    float* wto1 = wt_ + 3 * (size_t)DD * DD;
    float* wto2 = wt_ + 4 * (size_t)DD * DD;

    // 0) transpose weights -> [N][K]
    dim3 tb(32, 8), tg(32, 32);
    transpose_kernel<<<tg, tb>>>(Wq,  wtq);
    transpose_kernel<<<tg, tb>>>(Wk,  wtk);
    transpose_kernel<<<tg, tb>>>(Wv,  wtv);
    transpose_kernel<<<tg, tb>>>(Wo1, wto1);
    transpose_kernel<<<tg, tb>>>(Wo2, wto2);

    // 1) LN1
    ln_kernel<<<NTOK, 256>>>(x, g1, b1, h_);

    // 2) Q/K/V projections
    dim3 ggrid(DD / 128, NTOK / 128);
    mgemm_kernel<0, false><<<ggrid, 256>>>(h_, wtq, bq, h_, q_, NTOK, DD, DD);
    mgemm_kernel<0, false><<<ggrid, 256>>>(h_, wtk, bk, h_, k_, NTOK, DD, DD);
    mgemm_kernel<0, false><<<ggrid, 256>>>(h_, wtv, bv, h_, v_, NTOK, DD, DD);

    // 3) tensor-core flash attention + residual -> g_res
    cudaFuncSetAttribute(attn_mma_kernel, cudaFuncAttributeMaxDynamicSharedMemorySize, ATT2_SMEM);
    attn_mma_kernel<<<dim3(LL / 64, BB * HH), 128, ATT2_SMEM>>>(q_, k_, v_, mask, x, res_);

    // 4) LN2
    ln_kernel<<<NTOK, 256>>>(res_, g2, b2, ln2_);

    // 5) MLP up + GELU
    mgemm_kernel<1, false><<<ggrid, 256>>>(ln2_, wto1, bo1, ln2_, mlp_, NTOK, DD, DD);

    // 6) MLP down + bias + residual -> out
    mgemm_kernel<0, true><<<ggrid, 256>>>(mlp_, wto2, bo2, res_, out, NTOK, DD, DD);
}

// round 5
// speedup vs baseline: 3.4236x; 1.2266x over previous
#include <cuda_runtime.h>
#include <cuda.h>
#include <cuda_bf16.h>
#include <math.h>
#include <stdint.h>

#define BB 4
#define LL 2048
#define DD 1024
#define HH 16
#define DHH 64
#define NTOK (BB*LL)   // 8192 rows
#define D3  (3*DD)     // 3072

// ---------------- scratch (device globals; no allocation allowed) ----------------
__device__ __align__(16) __nv_bfloat16 g_h_hi  [NTOK*DD];
__device__ __align__(16) __nv_bfloat16 g_h_lo  [NTOK*DD];
__device__ __align__(16) __nv_bfloat16 g_qkv_hi[NTOK*D3];
__device__ __align__(16) __nv_bfloat16 g_qkv_lo[NTOK*D3];
__device__ __align__(16) __nv_bfloat16 g_ln2_hi[NTOK*DD];
__device__ __align__(16) __nv_bfloat16 g_ln2_lo[NTOK*DD];
__device__ __align__(16) __nv_bfloat16 g_mlp_hi[NTOK*DD];
__device__ __align__(16) __nv_bfloat16 g_mlp_lo[NTOK*DD];
__device__ __align__(16) __nv_bfloat16 g_wqkv_hi[3*DD*DD];
__device__ __align__(16) __nv_bfloat16 g_wqkv_lo[3*DD*DD];
__device__ __align__(16) __nv_bfloat16 g_w1_hi[DD*DD];
__device__ __align__(16) __nv_bfloat16 g_w1_lo[DD*DD];
__device__ __align__(16) __nv_bfloat16 g_w2_hi[DD*DD];
__device__ __align__(16) __nv_bfloat16 g_w2_lo[DD*DD];
__device__ __align__(16) float g_res [NTOK*DD];
__device__ __align__(16) float g_bqkv[D3];

// ============================ helpers ============================
__device__ __forceinline__ uint32_t smem_u32(const void* p) {
    uint32_t a;
    asm("{ .reg .u64 t; cvta.to.shared.u64 t, %1; cvt.u32.u64 %0, t; }" : "=r"(a) : "l"(p));
    return a;
}
__device__ __forceinline__ void mma_bf16(float* c, const uint32_t* a, const uint32_t* b) {
    asm volatile(
        "mma.sync.aligned.m16n8k16.row.col.f32.bf16.bf16.f32 "
        "{%0,%1,%2,%3}, {%4,%5,%6,%7}, {%8,%9}, {%0,%1,%2,%3};"
        : "+f"(c[0]), "+f"(c[1]), "+f"(c[2]), "+f"(c[3])
        : "r"(a[0]), "r"(a[1]), "r"(a[2]), "r"(a[3]), "r"(b[0]), "r"(b[1]));
}
__device__ __forceinline__ void ldsm_x4(uint32_t* r, uint32_t addr) {
    asm volatile("ldmatrix.sync.aligned.m8n8.x4.shared.b16 {%0,%1,%2,%3}, [%4];"
        : "=r"(r[0]), "=r"(r[1]), "=r"(r[2]), "=r"(r[3]) : "r"(addr));
}
__device__ __forceinline__ void ldsm_x2(uint32_t* r, uint32_t addr) {
    asm volatile("ldmatrix.sync.aligned.m8n8.x2.shared.b16 {%0,%1}, [%2];"
        : "=r"(r[0]), "=r"(r[1]) : "r"(addr));
}
__device__ __forceinline__ void ldsm_x2_t(uint32_t* r, uint32_t addr) {
    asm volatile("ldmatrix.sync.aligned.m8n8.x2.trans.shared.b16 {%0,%1}, [%2];"
        : "=r"(r[0]), "=r"(r[1]) : "r"(addr));
}
__device__ __forceinline__ void cp8(uint32_t dst, const void* src) {
    asm volatile("cp.async.ca.shared.global [%0], [%1], 8;" :: "r"(dst), "l"(src));
}
#define CP_COMMIT() asm volatile("cp.async.commit_group;" ::: "memory")
#define CP_WAIT0()  asm volatile("cp.async.wait_group 0;" ::: "memory")

// hi/lo bf16 split of a float4 -> two 8B stores each
__device__ __forceinline__ void cvt_store(__nv_bfloat16* hi, __nv_bfloat16* lo, float4 a) {
    __nv_bfloat162 h0 = __floats2bfloat162_rn(a.x, a.y);
    __nv_bfloat162 h1 = __floats2bfloat162_rn(a.z, a.w);
    __nv_bfloat162 l0 = __floats2bfloat162_rn(a.x - __bfloat162float(__low2bfloat16(h0)),
                                              a.y - __bfloat162float(__high2bfloat16(h0)));
    __nv_bfloat162 l1 = __floats2bfloat162_rn(a.z - __bfloat162float(__low2bfloat16(h1)),
                                              a.w - __bfloat162float(__high2bfloat16(h1)));
    *(__nv_bfloat162*)(hi)     = h0;
    *(__nv_bfloat162*)(hi + 2) = h1;
    *(__nv_bfloat162*)(lo)     = l0;
    *(__nv_bfloat162*)(lo + 2) = l1;
}
__device__ __forceinline__ void pack_hilo(uint32_t& ph, uint32_t& pl, float v0, float v1) {
    __nv_bfloat162 hh = __floats2bfloat162_rn(v0, v1);
    float f0 = __bfloat162float(__low2bfloat16(hh));
    float f1 = __bfloat162float(__high2bfloat16(hh));
    __nv_bfloat162 ll = __floats2bfloat162_rn(v0 - f0, v1 - f1);
    ph = *(uint32_t*)&hh;
    pl = *(uint32_t*)&ll;
}

// ============ bf16x3 GEMM, bf16 hi/lo inputs, cp.async double-buffered ============
// A [M,K] bf16 hi/lo, B [N,K] bf16 hi/lo. 128x128 tile, BK=32, 8 warps (2x4).
#define GS_STRIDE 40                     // bf16 per smem row (80B)
#define GT_BYTES  (128*GS_STRIDE*2)      // 10240 per tensor tile
#define GSTAGE_BYTES (4*GT_BYTES)        // Ahi,Alo,Bhi,Blo
#define BGEMM_SMEM (2*GSTAGE_BYTES)      // 81920

template<int ACT, bool RES, bool SPLIT>
__global__ void __launch_bounds__(256, 2)
bgemm_kernel(const __nv_bfloat16* __restrict__ Ah, const __nv_bfloat16* __restrict__ Al,
             const __nv_bfloat16* __restrict__ Bh, const __nv_bfloat16* __restrict__ Bl,
             const float* __restrict__ bias, const float* __restrict__ res,
             float* __restrict__ Cf, __nv_bfloat16* __restrict__ Ch,
             __nv_bfloat16* __restrict__ Cl, int M, int N, int K)
{
    extern __shared__ char dsm[];
    const uint32_t sb = smem_u32(dsm);

    const int tid  = threadIdx.x;
    const int wid  = tid >> 5;
    const int lane = tid & 31;
    const int wm   = wid >> 2;
    const int wn   = wid & 3;
    const int row0 = blockIdx.y * 128;
    const int col0 = blockIdx.x * 128;

    float acc[4][4][4];
    #pragma unroll
    for (int i = 0; i < 4; i++)
        #pragma unroll
        for (int j = 0; j < 4; j++)
            #pragma unroll
            for (int q = 0; q < 4; q++) acc[i][j][q] = 0.f;

    const uint32_t aoff = (uint32_t)(((lane & 15) * GS_STRIDE + ((lane >> 4) & 1) * 8) * 2);
    const uint32_t boff = (uint32_t)(((lane & 7)  * GS_STRIDE + ((lane >> 3) & 1) * 8) * 2);

    const int nkt = K / 32;

    // cp.async stage loader: 4 chunks of 8B per thread per tensor
    auto load_stage = [&](int i, int buf) {
        uint32_t s0 = sb + (uint32_t)buf * GSTAGE_BYTES;
        int kt = i * 32;
        #pragma unroll
        for (int u = 0; u < 4; u++) {
            int c   = tid + u * 256;          // 0..1023
            int row = c >> 3;
            int ch  = c & 7;                  // 8B unit
            uint32_t so = (uint32_t)(row * (GS_STRIDE * 2) + ch * 8);
            size_t ga = (size_t)(row0 + row) * K + kt + ch * 4;
            size_t gb = (size_t)(col0 + row) * K + kt + ch * 4;
            cp8(s0 + 0 * GT_BYTES + so, Ah + ga);
            cp8(s0 + 1 * GT_BYTES + so, Al + ga);
            cp8(s0 + 2 * GT_BYTES + so, Bh + gb);
            cp8(s0 + 3 * GT_BYTES + so, Bl + gb);
        }
        CP_COMMIT();
    };

    load_stage(0, 0);

    for (int i = 0; i < nkt; i++) {
        const int b = i & 1;
        CP_WAIT0();
        __syncthreads();
        if (i + 1 < nkt) load_stage(i + 1, 1 - b);

        const uint32_t sAh = sb + (uint32_t)b * GSTAGE_BYTES;
        const uint32_t sAl = sAh + GT_BYTES;
        const uint32_t sBh = sAh + 2 * GT_BYTES;
        const uint32_t sBl = sAh + 3 * GT_BYTES;

        #pragma unroll
        for (int ks = 0; ks < 32; ks += 16) {
            uint32_t ah[4][4], al[4][4];
            #pragma unroll
            for (int mt = 0; mt < 4; mt++) {
                uint32_t ro = (uint32_t)((wm * 64 + mt * 16) * (GS_STRIDE * 2)) + (uint32_t)(ks * 2);
                ldsm_x4(ah[mt], sAh + aoff + ro);
                ldsm_x4(al[mt], sAl + aoff + ro);
            }
            #pragma unroll
            for (int nt = 0; nt < 4; nt++) {
                uint32_t bh[2], bl[2];
                uint32_t ro = (uint32_t)((wn * 32 + nt * 8) * (GS_STRIDE * 2)) + (uint32_t)(ks * 2);
                ldsm_x2(bh, sBh + boff + ro);
                ldsm_x2(bl, sBl + boff + ro);
                #pragma unroll
                for (int mt = 0; mt < 4; mt++) {
                    mma_bf16(acc[mt][nt], ah[mt], bh);
                    mma_bf16(acc[mt][nt], ah[mt], bl);
                    mma_bf16(acc[mt][nt], al[mt], bh);
                }
            }
        }
    }

    const int er = lane >> 2;
    const int ec = (lane & 3) * 2;
    #pragma unroll
    for (int mt = 0; mt < 4; mt++) {
        #pragma unroll
        for (int half = 0; half < 2; half++) {
            int row = row0 + wm * 64 + mt * 16 + er + half * 8;
            #pragma unroll
            for (int nt = 0; nt < 4; nt++) {
                int col = col0 + wn * 32 + nt * 8 + ec;
                float v0 = acc[mt][nt][half * 2 + 0] + bias[col];
                float v1 = acc[mt][nt][half * 2 + 1] + bias[col + 1];
                if (ACT == 1) {
                    v0 = 0.5f * v0 * (1.0f + erff(v0 * 0.70710678118654752f));
                    v1 = 0.5f * v1 * (1.0f + erff(v1 * 0.70710678118654752f));
                }
                if (RES) {
                    const float* rp = res + (size_t)row * N;
                    v0 += rp[col]; v1 += rp[col + 1];
                }
                if (SPLIT) {
                    __nv_bfloat162 h2 = __floats2bfloat162_rn(v0, v1);
                    float f0 = __bfloat162float(__low2bfloat16(h2));
                    float f1 = __bfloat162float(__high2bfloat16(h2));
                    __nv_bfloat162 l2 = __floats2bfloat162_rn(v0 - f0, v1 - f1);
                    *(__nv_bfloat162*)(Ch + (size_t)row * N + col) = h2;
                    *(__nv_bfloat162*)(Cl + (size_t)row * N + col) = l2;
                } else {
                    float2 o; o.x = v0; o.y = v1;
                    *(float2*)(Cf + (size_t)row * N + col) = o;
                }
            }
        }
    }
}

// ---------------- weight transpose + hi/lo split: out[n][k] = split(in[k][n]) ----------------
__global__ void __launch_bounds__(256)
tsplit_kernel(const float* __restrict__ in, __nv_bfloat16* __restrict__ oh,
              __nv_bfloat16* __restrict__ ol)
{
    __shared__ float t[32][33];
    int bx = blockIdx.x * 32, by = blockIdx.y * 32;
    int x = bx + threadIdx.x;
    #pragma unroll
    for (int j = 0; j < 32; j += 8)
        t[threadIdx.y + j][threadIdx.x] = in[(size_t)(by + threadIdx.y + j) * DD + x];
    __syncthreads();
    int x2 = by + threadIdx.x;
    #pragma unroll
    for (int j = 0; j < 32; j += 8) {
        float v = t[threadIdx.x][threadIdx.y + j];
        size_t o = (size_t)(bx + threadIdx.y + j) * DD + x2;
        __nv_bfloat16 h = __float2bfloat16(v);
        oh[o] = h;
        ol[o] = __float2bfloat16(v - __bfloat162float(h));
    }
}

// ---------------- LayerNorm -> bf16 hi/lo ----------------
__global__ void __launch_bounds__(256)
ln_split_kernel(const float* __restrict__ in, const float* __restrict__ gam,
                const float* __restrict__ bet, __nv_bfloat16* __restrict__ oh,
                __nv_bfloat16* __restrict__ ol)
{
    size_t base = (size_t)blockIdx.x * DD;
    int t4 = threadIdx.x * 4;
    float4 v = *(const float4*)&in[base + t4];
    float s  = v.x + v.y + v.z + v.w;
    float s2 = v.x*v.x + v.y*v.y + v.z*v.z + v.w*v.w;
    #pragma unroll
    for (int o = 16; o; o >>= 1) {
        s  += __shfl_xor_sync(0xffffffffu, s,  o);
        s2 += __shfl_xor_sync(0xffffffffu, s2, o);
    }
    __shared__ float rs[8], rs2[8];
    __shared__ float smu, srstd;
    int w = threadIdx.x >> 5, lane = threadIdx.x & 31;
    if (lane == 0) { rs[w] = s; rs2[w] = s2; }
    __syncthreads();
    if (threadIdx.x == 0) {
        float S = 0.f, S2 = 0.f;
        #pragma unroll
        for (int i = 0; i < 8; i++) { S += rs[i]; S2 += rs2[i]; }
        float mu  = S * (1.0f / DD);
        float var = S2 * (1.0f / DD) - mu * mu;
        smu = mu;
        srstd = rsqrtf(var + 1e-6f);
    }
    __syncthreads();
    float mu = smu, rstd = srstd;
    float4 g4 = *(const float4*)&gam[t4];
    float4 b4 = *(const float4*)&bet[t4];
    float4 o;
    o.x = (v.x - mu) * rstd * g4.x + b4.x;
    o.y = (v.y - mu) * rstd * g4.y + b4.y;
    o.z = (v.z - mu) * rstd * g4.z + b4.z;
    o.w = (v.w - mu) * rstd * g4.w + b4.w;
    cvt_store(oh + base + t4, ol + base + t4, o);
}

// ============ tensor-core flash attention (bf16x3, bf16 hi/lo inputs) ============
// qkv packed [NTOK][3072]: q at +0, k at +1024, v at +2048 (per row).
#define ATSTRIDE 72
#define ATT2_SMEM (6*64*ATSTRIDE*2 + 256)

__global__ void __launch_bounds__(128, 3)
attn_mma_kernel(const __nv_bfloat16* __restrict__ qkv_hi,
                const __nv_bfloat16* __restrict__ qkv_lo,
                const int* __restrict__ mask,
                const float* __restrict__ x, float* __restrict__ res)
{
    extern __shared__ char sm8[];
    __nv_bfloat16* Qh = (__nv_bfloat16*)sm8;
    __nv_bfloat16* Ql = Qh + 64 * ATSTRIDE;
    __nv_bfloat16* Kh = Ql + 64 * ATSTRIDE;
    __nv_bfloat16* Kl = Kh + 64 * ATSTRIDE;
    __nv_bfloat16* Vh = Kl + 64 * ATSTRIDE;
    __nv_bfloat16* Vl = Vh + 64 * ATSTRIDE;
    float* maskadd = (float*)(Vl + 64 * ATSTRIDE);

    const int tid  = threadIdx.x;
    const int wid  = tid >> 5;
    const int lane = tid & 31;
    const int b    = blockIdx.y >> 4;
    const int h    = blockIdx.y & 15;
    const int q0   = blockIdx.x * 64;
    const int er   = lane >> 2;
    const int qc   = lane & 3;

    const int lr = tid >> 1;            // 0..63
    const int lc = (tid & 1) * 32;      // 0 or 32

    // ---- load Q tile 64x64 bf16 hi/lo ----
    {
        size_t gq = (size_t)(b * LL + q0 + lr) * D3 + h * DHH + lc;
        #pragma unroll
        for (int j = 0; j < 4; j++) {
            *(uint4*)&Qh[lr * ATSTRIDE + lc + 8*j] = *(const uint4*)(qkv_hi + gq + 8*j);
            *(uint4*)&Ql[lr * ATSTRIDE + lc + 8*j] = *(const uint4*)(qkv_lo + gq + 8*j);
        }
    }
    __syncthreads();

    const uint32_t sQh = smem_u32(Qh), sQl = smem_u32(Ql);
    const uint32_t sKh = smem_u32(Kh), sKl = smem_u32(Kl);
    const uint32_t sVh = smem_u32(Vh), sVl = smem_u32(Vl);
    const uint32_t aoff = (uint32_t)(((lane & 15) * ATSTRIDE + ((lane >> 4) & 1) * 8) * 2);
    const uint32_t boff = (uint32_t)(((lane & 7)  * ATSTRIDE + ((lane >> 3) & 1) * 8) * 2);
    uint32_t qh[4][4], qlo[4][4];
    #pragma unroll
    for (int s = 0; s < 4; s++) {
        uint32_t ro = (uint32_t)((wid * 16) * (ATSTRIDE * 2)) + (uint32_t)(s * 32);
        ldsm_x4(qh[s],  sQh + aoff + ro);
        ldsm_x4(qlo[s], sQl + aoff + ro);
    }

    float m0 = -1e30f, m1 = -1e30f, l0 = 0.f, l1 = 0.f;
    float o[8][4];
    #pragma unroll
    for (int j = 0; j < 8; j++)
        #pragma unroll
        for (int t = 0; t < 4; t++) o[j][t] = 0.f;

    for (int kt = 0; kt < LL; kt += 64) {
        __syncthreads();
        {
            size_t gk = (size_t)(b * LL + kt + lr) * D3 + h * DHH + lc;
            const __nv_bfloat16* khp = qkv_hi + gk + DD;
            const __nv_bfloat16* klp = qkv_lo + gk + DD;
            const __nv_bfloat16* vhp = qkv_hi + gk + 2 * DD;
            const __nv_bfloat16* vlp = qkv_lo + gk + 2 * DD;
            #pragma unroll
            for (int j = 0; j < 4; j++) {
                *(uint4*)&Kh[lr * ATSTRIDE + lc + 8*j] = *(const uint4*)(khp + 8*j);
                *(uint4*)&Kl[lr * ATSTRIDE + lc + 8*j] = *(const uint4*)(klp + 8*j);
                *(uint4*)&Vh[lr * ATSTRIDE + lc + 8*j] = *(const uint4*)(vhp + 8*j);
                *(uint4*)&Vl[lr * ATSTRIDE + lc + 8*j] = *(const uint4*)(vlp + 8*j);
            }
            if (tid < 64)
                maskadd[tid] = (1.0f - (float)mask[b * LL + kt + tid]) * (-1e30f);
        }
        __syncthreads();

        // ---- S = Q K^T (bf16x3) ----
        float s[8][4];
        #pragma unroll
        for (int j = 0; j < 8; j++)
            #pragma unroll
            for (int t = 0; t < 4; t++) s[j][t] = 0.f;
        #pragma unroll
        for (int ks = 0; ks < 4; ks++) {
            #pragma unroll
            for (int j = 0; j < 8; j++) {
                uint32_t kh2[2], kl2[2];
                uint32_t ro = (uint32_t)((8 * j) * (ATSTRIDE * 2)) + (uint32_t)(ks * 32);
                ldsm_x2(kh2, sKh + boff + ro);
                ldsm_x2(kl2, sKl + boff + ro);
                mma_bf16(s[j], qh[ks],  kh2);
                mma_bf16(s[j], qh[ks],  kl2);
                mma_bf16(s[j], qlo[ks], kh2);
            }
        }

        // ---- online softmax ----
        float mx0 = -1e30f, mx1 = -1e30f;
        #pragma unroll
        for (int j = 0; j < 8; j++) {
            float ma0 = maskadd[8 * j + 2 * qc];
            float ma1 = maskadd[8 * j + 2 * qc + 1];
            s[j][0] = s[j][0] * 0.125f + ma0;
            s[j][1] = s[j][1] * 0.125f + ma1;
            s[j][2] = s[j][2] * 0.125f + ma0;
            s[j][3] = s[j][3] * 0.125f + ma1;
            mx0 = fmaxf(mx0, fmaxf(s[j][0], s[j][1]));
            mx1 = fmaxf(mx1, fmaxf(s[j][2], s[j][3]));
        }
        mx0 = fmaxf(mx0, __shfl_xor_sync(0xffffffffu, mx0, 1));
        mx0 = fmaxf(mx0, __shfl_xor_sync(0xffffffffu, mx0, 2));
        mx1 = fmaxf(mx1, __shfl_xor_sync(0xffffffffu, mx1, 1));
        mx1 = fmaxf(mx1, __shfl_xor_sync(0xffffffffu, mx1, 2));
        float mn0 = fmaxf(m0, mx0), mn1 = fmaxf(m1, mx1);
        float c0 = __expf(m0 - mn0), c1 = __expf(m1 - mn1);
        m0 = mn0; m1 = mn1;
        float ls0 = 0.f, ls1 = 0.f;
        #pragma unroll
        for (int j = 0; j < 8; j++) {
            s[j][0] = __expf(s[j][0] - mn0);
            s[j][1] = __expf(s[j][1] - mn0);
            s[j][2] = __expf(s[j][2] - mn1);
            s[j][3] = __expf(s[j][3] - mn1);
            ls0 += s[j][0] + s[j][1];
            ls1 += s[j][2] + s[j][3];
        }
        l0 = l0 * c0 + ls0;
        l1 = l1 * c1 + ls1;
        #pragma unroll
        for (int j = 0; j < 8; j++) {
            o[j][0] *= c0; o[j][1] *= c0;
            o[j][2] *= c1; o[j][3] *= c1;
        }

        // ---- O += P @ V ----
        #pragma unroll
        for (int ks = 0; ks < 4; ks++) {
            uint32_t ph[4], pl[4];
            pack_hilo(ph[0], pl[0], s[2*ks][0],   s[2*ks][1]);
            pack_hilo(ph[1], pl[1], s[2*ks][2],   s[2*ks][3]);
            pack_hilo(ph[2], pl[2], s[2*ks+1][0], s[2*ks+1][1]);
            pack_hilo(ph[3], pl[3], s[2*ks+1][2], s[2*ks+1][3]);
            uint32_t vrow = (uint32_t)((16 * ks + (lane & 7) + 8 * ((lane >> 3) & 1)) * (ATSTRIDE * 2));
            #pragma unroll
            for (int j = 0; j < 8; j++) {
                uint32_t vh2[2], vl2[2];
                uint32_t vro = vrow + (uint32_t)(16 * j);
                ldsm_x2_t(vh2, sVh + vro);
                ldsm_x2_t(vl2, sVl + vro);
                mma_bf16(o[j], ph, vh2);
                mma_bf16(o[j], ph, vl2);
                mma_bf16(o[j], pl, vh2);
            }
        }
    }

    // ---- finalize ----
    l0 += __shfl_xor_sync(0xffffffffu, l0, 1);
    l0 += __shfl_xor_sync(0xffffffffu, l0, 2);
    l1 += __shfl_xor_sync(0xffffffffu, l1, 1);
    l1 += __shfl_xor_sync(0xffffffffu, l1, 2);
    float i0 = 1.0f / l0, i1 = 1.0f / l1;

    const int row0 = q0 + wid * 16 + er;
    #pragma unroll
    for (int j = 0; j < 8; j++) {
        int col = h * DHH + 8 * j + 2 * qc;
        size_t base0 = (size_t)(b * LL + row0) * DD + col;
        size_t base1 = base0 + 8 * (size_t)DD;
        float2 r0, r1;
        r0.x = o[j][0] * i0 + x[base0];
        r0.y = o[j][1] * i0 + x[base0 + 1];
        r1.x = o[j][2] * i1 + x[base1];
        r1.y = o[j][3] * i1 + x[base1 + 1];
        *(float2*)&res[base0] = r0;
        *(float2*)&res[base1] = r1;
    }
}

// ---------------- launch ----------------
extern "C" void kernel_launch(void* const* d_in, const int* in_sizes, int n_in,
                              void* d_out, int out_size)
{
    const float* x    = (const float*)d_in[0];
    const int*   mask = (const int*)  d_in[1];
    const float* Wq   = (const float*)d_in[2];
    const float* bq   = (const float*)d_in[3];
    const float* Wk   = (const float*)d_in[4];
    const float* bk   = (const float*)d_in[5];
    const float* Wv   = (const float*)d_in[6];
    const float* bv   = (const float*)d_in[7];
    const float* g1   = (const float*)d_in[8];
    const float* b1   = (const float*)d_in[9];
    const float* g2   = (const float*)d_in[10];
    const float* b2   = (const float*)d_in[11];
    const float* Wo1  = (const float*)d_in[12];
    const float* bo1  = (const float*)d_in[13];
    const float* Wo2  = (const float*)d_in[14];
    const float* bo2  = (const float*)d_in[15];
    float* out = (float*)d_out;

    __nv_bfloat16 *hhi, *hlo, *qkvhi, *qkvlo, *ln2hi, *ln2lo, *mlphi, *mlplo;
    __nv_bfloat16 *wqkvhi, *wqkvlo, *w1hi, *w1lo, *w2hi, *w2lo;
    float *res_, *bqkv;
    cudaGetSymbolAddress((void**)&hhi,    g_h_hi);
    cudaGetSymbolAddress((void**)&hlo,    g_h_lo);
    cudaGetSymbolAddress((void**)&qkvhi,  g_qkv_hi);
    cudaGetSymbolAddress((void**)&qkvlo,  g_qkv_lo);
    cudaGetSymbolAddress((void**)&ln2hi,  g_ln2_hi);
    cudaGetSymbolAddress((void**)&ln2lo,  g_ln2_lo);
    cudaGetSymbolAddress((void**)&mlphi,  g_mlp_hi);
    cudaGetSymbolAddress((void**)&mlplo,  g_mlp_lo);
    cudaGetSymbolAddress((void**)&wqkvhi, g_wqkv_hi);
    cudaGetSymbolAddress((void**)&wqkvlo, g_wqkv_lo);
    cudaGetSymbolAddress((void**)&w1hi,   g_w1_hi);
    cudaGetSymbolAddress((void**)&w1lo,   g_w1_lo);
    cudaGetSymbolAddress((void**)&w2hi,   g_w2_hi);
    cudaGetSymbolAddress((void**)&w2lo,   g_w2_lo);
    cudaGetSymbolAddress((void**)&res_,   g_res);
    cudaGetSymbolAddress((void**)&bqkv,   g_bqkv);

    cudaFuncSetAttribute(bgemm_kernel<0, false, true>,  cudaFuncAttributeMaxDynamicSharedMemorySize, BGEMM_SMEM);
    cudaFuncSetAttribute(bgemm_kernel<1, false, true>,  cudaFuncAttributeMaxDynamicSharedMemorySize, BGEMM_SMEM);
    cudaFuncSetAttribute(bgemm_kernel<0, true,  false>, cudaFuncAttributeMaxDynamicSharedMemorySize, BGEMM_SMEM);
    cudaFuncSetAttribute(attn_mma_kernel, cudaFuncAttributeMaxDynamicSharedMemorySize, ATT2_SMEM);

    // 0) weight prep: transpose + hi/lo split; bias concat
    dim3 tb(32, 8), tg(32, 32);
    tsplit_kernel<<<tg, tb>>>(Wq,  wqkvhi + 0 * (size_t)DD * DD, wqkvlo + 0 * (size_t)DD * DD);
    tsplit_kernel<<<tg, tb>>>(Wk,  wqkvhi + 1 * (size_t)DD * DD, wqkvlo + 1 * (size_t)DD * DD);
    tsplit_kernel<<<tg, tb>>>(Wv,  wqkvhi + 2 * (size_t)DD * DD, wqkvlo + 2 * (size_t)DD * DD);
    tsplit_kernel<<<tg, tb>>>(Wo1, w1hi, w1lo);
    tsplit_kernel<<<tg, tb>>>(Wo2, w2hi, w2lo);
    cudaMemcpyAsync(bqkv,        bq, DD * sizeof(float), cudaMemcpyDeviceToDevice, 0);
    cudaMemcpyAsync(bqkv + DD,   bk, DD * sizeof(float), cudaMemcpyDeviceToDevice, 0);
    cudaMemcpyAsync(bqkv + 2*DD, bv, DD * sizeof(float), cudaMemcpyDeviceToDevice, 0);

    // 1) LN1 -> bf16 hi/lo
    ln_split_kernel<<<NTOK, 256>>>(x, g1, b1, hhi, hlo);

    // 2) fused QKV projection -> packed qkv bf16 hi/lo
    bgemm_kernel<0, false, true><<<dim3(D3 / 128, NTOK / 128), 256, BGEMM_SMEM>>>(
        hhi, hlo, wqkvhi, wqkvlo, bqkv, nullptr, nullptr, qkvhi, qkvlo, NTOK, D3, DD);

    // 3) flash attention + residual -> res (fp32)
    attn_mma_kernel<<<dim3(LL / 64, BB * HH), 128, ATT2_SMEM>>>(qkvhi, qkvlo, mask, x, res_);

    // 4) LN2 -> bf16 hi/lo
    ln_split_kernel<<<NTOK, 256>>>(res_, g2, b2, ln2hi, ln2lo);

    // 5) MLP up + GELU -> bf16 hi/lo
    bgemm_kernel<1, false, true><<<dim3(DD / 128, NTOK / 128), 256, BGEMM_SMEM>>>(
        ln2hi, ln2lo, w1hi, w1lo, bo1, nullptr, nullptr, mlphi, mlplo, NTOK, DD, DD);

    // 6) MLP down + bias + residual -> out (fp32)
    bgemm_kernel<0, true, false><<<dim3(DD / 128, NTOK / 128), 256, BGEMM_SMEM>>>(
        mlphi, mlplo, w2hi, w2lo, bo2, res_, out, nullptr, nullptr, NTOK, DD, DD);
}